// round 11
// baseline (speedup 1.0000x reference)
#include <cuda_runtime.h>
#include <cuda_fp16.h>
#include <stdint.h>
#include <math.h>

#define NMAX 50000
#define EMAX 800000
#define BMAX 128

// ---------------- scratch ----------------
__device__ __half  d_Xh  [NMAX * 128];   // input x converted to fp16
__device__ __half2 d_XHh [NMAX * 64];    // GEMM output fp16
__device__ __half2 d_H1h [NMAX * 64];    // layer-1 output fp16
__device__ __half  d_Wt1 [128 * 128];    // W1^T fp16 [n][k]
__device__ __half  d_Wt2 [128 * 128];    // W2^T fp16 [n][k]
__device__ float   d_OUT2[NMAX * 32];
__device__ float   d_ASRC[NMAX * 4];
__device__ float   d_ADST[NMAX * 4];
__device__ int     d_deg   [NMAX];
__device__ int     d_rowptr[NMAX + 1];
__device__ int     d_cursor[NMAX];
__device__ int     d_col   [EMAX + NMAX];
__device__ float   d_gsum  [BMAX * 32];
__device__ int     d_bsum  [64];

// ---------------- init + weight prep + X convert ----------------
__global__ void k_init(const float* __restrict__ x,
                       const float* __restrict__ W1, const float* __restrict__ W2,
                       int N, int B) {
    int i0 = blockIdx.x * blockDim.x + threadIdx.x;
    int stride = gridDim.x * blockDim.x;
    for (int t = i0; t < N; t += stride) d_deg[t] = 1;   // self loop pre-counted
    for (int t = i0; t < B * 32; t += stride) d_gsum[t] = 0.f;
    for (int t = i0; t < 16384; t += stride) {
        int n = t >> 7, k = t & 127;
        d_Wt1[n * 128 + k] = __float2half_rn(W1[k * 128 + n]);
        d_Wt2[n * 128 + k] = __float2half_rn(W2[k * 128 + n]);
    }
    __half2* Xh2 = (__half2*)d_Xh;
    int total = N * 64;
    for (int t = i0; t < total; t += stride) {
        float2 v = ((const float2*)x)[t];
        Xh2[t] = __floats2half2_rn(v.x, v.y);
    }
}

// ---------------- cp.async helpers ----------------
__device__ __forceinline__ void cp16(void* smem_dst, const void* gmem_src) {
    unsigned sa = (unsigned)__cvta_generic_to_shared(smem_dst);
    asm volatile("cp.async.cg.shared.global [%0], [%1], 16;" :: "r"(sa), "l"(gmem_src));
}
__device__ __forceinline__ void cp_commit() {
    asm volatile("cp.async.commit_group;");
}
template <int NN>
__device__ __forceinline__ void cp_wait() {
    asm volatile("cp.async.wait_group %0;" :: "n"(NN));
}

// ---------------- tensor-core GEMM + fused attention dots (2-stage cp.async) ----------------
__global__ void __launch_bounds__(256, 2) k_gemm_att(
    const __half* __restrict__ Xin, const __half* __restrict__ Wt,
    const float* __restrict__ att_s, const float* __restrict__ att_d,
    int nrows)
{
    extern __shared__ __half smem[];
    const int STG = 128 * 40;
    __half* Xs[2] = { smem,       smem + 2 * STG };
    __half* Ws[2] = { smem + STG, smem + 3 * STG };

    int tid = threadIdx.x;
    int wid = tid >> 5, lane = tid & 31;
    int g = lane >> 2, t = lane & 3;
    int wr = wid >> 1, wc = wid & 1;
    int rowBase = blockIdx.x * 128;

    int lr0 = tid >> 2,         lc0 = (tid & 3) * 8;
    int lr1 = (tid + 256) >> 2, lc1 = ((tid + 256) & 3) * 8;
    int gxr0 = min(rowBase + lr0, nrows - 1);
    int gxr1 = min(rowBase + lr1, nrows - 1);

    float acc[2][8][4];
#pragma unroll
    for (int mi = 0; mi < 2; mi++)
#pragma unroll
        for (int ni = 0; ni < 8; ni++)
#pragma unroll
            for (int q = 0; q < 4; q++) acc[mi][ni][q] = 0.f;

#pragma unroll
    for (int pt = 0; pt < 2; pt++) {
        int k0 = pt * 32;
        cp16(Xs[pt] + lr0 * 40 + lc0, Xin + gxr0 * 128 + k0 + lc0);
        cp16(Xs[pt] + lr1 * 40 + lc1, Xin + gxr1 * 128 + k0 + lc1);
        cp16(Ws[pt] + lr0 * 40 + lc0, Wt + lr0 * 128 + k0 + lc0);
        cp16(Ws[pt] + lr1 * 40 + lc1, Wt + lr1 * 128 + k0 + lc1);
        cp_commit();
    }

#pragma unroll
    for (int kt = 0; kt < 4; kt++) {
        if (kt < 3) cp_wait<1>(); else cp_wait<0>();
        __syncthreads();
        int buf = kt & 1;
        __half* Xb = Xs[buf];
        __half* Wb = Ws[buf];
#pragma unroll
        for (int ks = 0; ks < 2; ks++) {
            int kb = ks * 16;
            uint32_t a[2][4];
#pragma unroll
            for (int mi = 0; mi < 2; mi++) {
                int ar = wr * 32 + mi * 16 + g;
                a[mi][0] = *(const uint32_t*)&Xb[ar * 40 + kb + 2 * t];
                a[mi][1] = *(const uint32_t*)&Xb[(ar + 8) * 40 + kb + 2 * t];
                a[mi][2] = *(const uint32_t*)&Xb[ar * 40 + kb + 2 * t + 8];
                a[mi][3] = *(const uint32_t*)&Xb[(ar + 8) * 40 + kb + 2 * t + 8];
            }
#pragma unroll
            for (int ni = 0; ni < 8; ni++) {
                int bn = wc * 64 + ni * 8 + g;
                uint32_t b0 = *(const uint32_t*)&Wb[bn * 40 + kb + 2 * t];
                uint32_t b1 = *(const uint32_t*)&Wb[bn * 40 + kb + 2 * t + 8];
#pragma unroll
                for (int mi = 0; mi < 2; mi++) {
                    asm volatile(
                        "mma.sync.aligned.m16n8k16.row.col.f32.f16.f16.f32 "
                        "{%0,%1,%2,%3}, {%4,%5,%6,%7}, {%8,%9}, {%0,%1,%2,%3};"
                        : "+f"(acc[mi][ni][0]), "+f"(acc[mi][ni][1]),
                          "+f"(acc[mi][ni][2]), "+f"(acc[mi][ni][3])
                        : "r"(a[mi][0]), "r"(a[mi][1]), "r"(a[mi][2]), "r"(a[mi][3]),
                          "r"(b0), "r"(b1));
                }
            }
        }
        if (kt < 2) {
            __syncthreads();
            int k0 = (kt + 2) * 32;
            cp16(Xs[buf] + lr0 * 40 + lc0, Xin + gxr0 * 128 + k0 + lc0);
            cp16(Xs[buf] + lr1 * 40 + lc1, Xin + gxr1 * 128 + k0 + lc1);
            cp16(Ws[buf] + lr0 * 40 + lc0, Wt + lr0 * 128 + k0 + lc0);
            cp16(Ws[buf] + lr1 * 40 + lc1, Wt + lr1 * 128 + k0 + lc1);
            cp_commit();
        }
    }

    // ---- epilogue: attention dots, direct global store ----
#pragma unroll
    for (int mi = 0; mi < 2; mi++) {
        float ps[2][2] = {{0.f, 0.f}, {0.f, 0.f}};
        float pd[2][2] = {{0.f, 0.f}, {0.f, 0.f}};
#pragma unroll
        for (int ni = 0; ni < 8; ni++) {
            int col = wc * 64 + ni * 8 + 2 * t;
            float s0 = att_s[col], s1 = att_s[col + 1];
            float dd0 = att_d[col], dd1 = att_d[col + 1];
            int hl = ni >> 2;
            ps[0][hl] += acc[mi][ni][0] * s0 + acc[mi][ni][1] * s1;
            ps[1][hl] += acc[mi][ni][2] * s0 + acc[mi][ni][3] * s1;
            pd[0][hl] += acc[mi][ni][0] * dd0 + acc[mi][ni][1] * dd1;
            pd[1][hl] += acc[mi][ni][2] * dd0 + acc[mi][ni][3] * dd1;
        }
#pragma unroll
        for (int o = 1; o <= 2; o <<= 1) {
#pragma unroll
            for (int rh = 0; rh < 2; rh++)
#pragma unroll
                for (int hl = 0; hl < 2; hl++) {
                    ps[rh][hl] += __shfl_xor_sync(0xffffffffu, ps[rh][hl], o);
                    pd[rh][hl] += __shfl_xor_sync(0xffffffffu, pd[rh][hl], o);
                }
        }
        if (t == 0) {
            int gr = rowBase + wr * 32 + mi * 16 + g;
            if (gr < nrows) {
                d_ASRC[gr * 4 + 2 * wc]     = ps[0][0];
                d_ASRC[gr * 4 + 2 * wc + 1] = ps[0][1];
                d_ADST[gr * 4 + 2 * wc]     = pd[0][0];
                d_ADST[gr * 4 + 2 * wc + 1] = pd[0][1];
            }
            if (gr + 8 < nrows) {
                d_ASRC[(gr + 8) * 4 + 2 * wc]     = ps[1][0];
                d_ASRC[(gr + 8) * 4 + 2 * wc + 1] = ps[1][1];
                d_ADST[(gr + 8) * 4 + 2 * wc]     = pd[1][0];
                d_ADST[(gr + 8) * 4 + 2 * wc + 1] = pd[1][1];
            }
        }
    }
#pragma unroll
    for (int mi = 0; mi < 2; mi++) {
        int r0 = rowBase + wr * 32 + mi * 16 + g;
#pragma unroll
        for (int ni = 0; ni < 8; ni++) {
            int cp = wc * 32 + ni * 4 + t;
            if (r0 < nrows)
                d_XHh[r0 * 64 + cp] = __floats2half2_rn(acc[mi][ni][0], acc[mi][ni][1]);
            if (r0 + 8 < nrows)
                d_XHh[(r0 + 8) * 64 + cp] = __floats2half2_rn(acc[mi][ni][2], acc[mi][ni][3]);
        }
    }
}

// ---------------- CSR build ----------------
__global__ void k_deg(const int* __restrict__ ei, int E) {
    int i = blockIdx.x * blockDim.x + threadIdx.x;
    if (i >= E) return;
    atomicAdd(&d_deg[ei[E + i]], 1);
}

// phase 1: block-local inclusive scan -> rowptr[i+1] (pre-offset), block total -> d_bsum
__global__ void __launch_bounds__(1024) k_scan1(int N) {
    __shared__ int swarp[32];
    int b = blockIdx.x;
    int tid = threadIdx.x, lane = tid & 31, wid = tid >> 5;
    int i = b * 1024 + tid;
    int v = (i < N) ? d_deg[i] : 0;
    int x = v;
#pragma unroll
    for (int o = 1; o < 32; o <<= 1) {
        int t = __shfl_up_sync(0xffffffffu, x, o);
        if (lane >= o) x += t;
    }
    if (lane == 31) swarp[wid] = x;
    __syncthreads();
    if (wid == 0) {
        int y = swarp[lane];
#pragma unroll
        for (int o = 1; o < 32; o <<= 1) {
            int t = __shfl_up_sync(0xffffffffu, y, o);
            if (lane >= o) y += t;
        }
        swarp[lane] = y;
    }
    __syncthreads();
    int incl = x + (wid > 0 ? swarp[wid - 1] : 0);
    if (i < N) d_rowptr[i + 1] = incl;
    if (tid == 1023) d_bsum[b] = incl;
}

// phase 2+3 fused: warp-complete 64-wide scan (all shuffles run with full warps)
__global__ void __launch_bounds__(1024) k_scan3(int N) {
    __shared__ int s_incl[64];
    int b = blockIdx.x;
    int nb = gridDim.x;
    int tid = threadIdx.x;
    if (tid < 64) {                       // two FULL warps
        int v = (tid < nb) ? d_bsum[tid] : 0;
        int x = v;
#pragma unroll
        for (int o = 1; o < 32; o <<= 1) {
            int t = __shfl_up_sync(0xffffffffu, x, o);
            if ((tid & 31) >= o) x += t;
        }
        s_incl[tid] = x;                  // warp-local inclusive
    }
    __syncthreads();
    int base = (b < 32) ? 0 : s_incl[31];
    int off = base + s_incl[b] - d_bsum[b];   // exclusive prefix of block b
    int i = b * 1024 + tid;
    if (i >= N) return;
    int rp = d_rowptr[i + 1] + off;
    d_rowptr[i + 1] = rp;
    d_cursor[i] = rp - d_deg[i];
    if (i == 0) d_rowptr[0] = 0;
}

// edges via cursor atomic; self loop takes guaranteed-last slot (no atomic)
__global__ void k_fill(const int* __restrict__ ei, int E, int N) {
    int i = blockIdx.x * blockDim.x + threadIdx.x;
    int T = E + N;
    if (i >= T) return;
    if (i < E) {
        int s = ei[i], dd = ei[E + i];
        int pos = atomicAdd(&d_cursor[dd], 1);
        d_col[pos] = s;
    } else {
        int n = i - E;
        d_col[d_rowptr[n + 1] - 1] = n;
    }
}

// ---------------- GAT aggregation: warp per node, lane owns 4 channels ----------------
template <bool LAYER2>
__global__ void __launch_bounds__(128) k_agg(
    const float* __restrict__ bias, void* __restrict__ OUT, int N)
{
    __shared__ float4 s_e4[4][32];
    __shared__ int    s_src[4][32];

    int tid = threadIdx.x;
    int w = tid >> 5, lane = tid & 31;
    int n = blockIdx.x * 4 + w;
    if (n >= N) return;
    int h = lane >> 3;

    int start = d_rowptr[n], end = d_rowptr[n + 1];
    float4 ad = ((const float4*)d_ADST)[n];

    float m = -INFINITY, den = 0.f;
    float4 acc = make_float4(0.f, 0.f, 0.f, 0.f);
    const float* se = (const float*)&s_e4[w][0];
    const int*   ss = &s_src[w][0];
    const uint2* XH8 = (const uint2*)d_XHh;

    for (int k0 = start; k0 < end; k0 += 32) {
        int len = min(32, end - k0);
        float4 e4 = make_float4(-INFINITY, -INFINITY, -INFINITY, -INFINITY);
        int s = 0;
        if (lane < len) {
            s = __ldg(&d_col[k0 + lane]);
            float4 as = __ldg(&((const float4*)d_ASRC)[s]);
            e4.x = as.x + ad.x; e4.x = e4.x > 0.f ? e4.x : 0.2f * e4.x;
            e4.y = as.y + ad.y; e4.y = e4.y > 0.f ? e4.y : 0.2f * e4.y;
            e4.z = as.z + ad.z; e4.z = e4.z > 0.f ? e4.z : 0.2f * e4.z;
            e4.w = as.w + ad.w; e4.w = e4.w > 0.f ? e4.w : 0.2f * e4.w;
        }
        s_src[w][lane] = s;
        s_e4[w][lane] = e4;

        float4 mx = e4;
#pragma unroll
        for (int o = 16; o >= 1; o >>= 1) {
            mx.x = fmaxf(mx.x, __shfl_xor_sync(0xffffffffu, mx.x, o));
            mx.y = fmaxf(mx.y, __shfl_xor_sync(0xffffffffu, mx.y, o));
            mx.z = fmaxf(mx.z, __shfl_xor_sync(0xffffffffu, mx.z, o));
            mx.w = fmaxf(mx.w, __shfl_xor_sync(0xffffffffu, mx.w, o));
        }
        float cmh = (h == 0) ? mx.x : (h == 1) ? mx.y : (h == 2) ? mx.z : mx.w;
        float cm = fmaxf(m, cmh);
        float scale = __expf(m - cm);
        acc.x *= scale; acc.y *= scale; acc.z *= scale; acc.w *= scale;
        den *= scale;

        __syncwarp();
#pragma unroll 4
        for (int j = 0; j < len; j++) {
            float p = __expf(se[j * 4 + h] - cm);
            den += p;
            uint2 r = __ldg(&XH8[ss[j] * 32 + lane]);
            float2 f0 = __half22float2(*(const __half2*)&r.x);
            float2 f1 = __half22float2(*(const __half2*)&r.y);
            acc.x = fmaf(p, f0.x, acc.x);
            acc.y = fmaf(p, f0.y, acc.y);
            acc.z = fmaf(p, f1.x, acc.z);
            acc.w = fmaf(p, f1.y, acc.w);
        }
        m = cm;
        __syncwarp();
    }

    float inv = 1.f / (den + 1e-16f);
    float4 val = make_float4(acc.x * inv, acc.y * inv, acc.z * inv, acc.w * inv);

    if (!LAYER2) {
        float4 b4 = ((const float4*)bias)[lane];
        val.x = fmaxf(val.x + b4.x, 0.f);
        val.y = fmaxf(val.y + b4.y, 0.f);
        val.z = fmaxf(val.z + b4.z, 0.f);
        val.w = fmaxf(val.w + b4.w, 0.f);
        __half2 h0 = __floats2half2_rn(val.x, val.y);
        __half2 h1 = __floats2half2_rn(val.z, val.w);
        uint2 p; p.x = *(uint32_t*)&h0; p.y = *(uint32_t*)&h1;
        ((uint2*)OUT)[n * 32 + lane] = p;     // fp16 H1
    } else {
#pragma unroll
        for (int o = 8; o <= 16; o <<= 1) {
            val.x += __shfl_xor_sync(0xffffffffu, val.x, o);
            val.y += __shfl_xor_sync(0xffffffffu, val.y, o);
            val.z += __shfl_xor_sync(0xffffffffu, val.z, o);
            val.w += __shfl_xor_sync(0xffffffffu, val.w, o);
        }
        if (lane < 8) {
            float4 b4 = ((const float4*)bias)[lane];
            float4 o4 = make_float4(0.25f * val.x + b4.x, 0.25f * val.y + b4.y,
                                    0.25f * val.z + b4.z, 0.25f * val.w + b4.w);
            ((float4*)OUT)[n * 8 + lane] = o4;
        }
    }
}

// ---------------- global mean pool ----------------
__global__ void k_pool(const float* __restrict__ OUT2,
                       const int* __restrict__ batch, int N)
{
    int perBlock = (N + gridDim.x - 1) / gridDim.x;
    int n0 = blockIdx.x * perBlock;
    int n1 = min(N, n0 + perBlock);
    int ch  = threadIdx.x & 31;
    int sub = threadIdx.x >> 5;
    float sum = 0.f;
    int curb = -1;
    for (int n = n0 + sub; n < n1; n += 8) {
        int b = batch[n];
        if (b != curb) {
            if (curb >= 0) atomicAdd(&d_gsum[curb * 32 + ch], sum);
            curb = b; sum = 0.f;
        }
        sum += OUT2[n * 32 + ch];
    }
    if (curb >= 0) atomicAdd(&d_gsum[curb * 32 + ch], sum);
}

// ---------------- final MLP ----------------
__global__ void k_mlp(const int* __restrict__ batch, int N,
                      const float* __restrict__ stats,
                      const float* __restrict__ Wm1, const float* __restrict__ bm1,
                      const float* __restrict__ Wm2, const float* __restrict__ bm2,
                      float* __restrict__ out, int B)
{
    int g = threadIdx.x;
    if (g >= B) return;
    int lo0 = 0, hi0 = N;
    while (lo0 < hi0) { int mid = (lo0 + hi0) >> 1; if (batch[mid] < g) lo0 = mid + 1; else hi0 = mid; }
    int lo1 = lo0, hi1 = N;
    while (lo1 < hi1) { int mid = (lo1 + hi1) >> 1; if (batch[mid] < g + 1) lo1 = mid + 1; else hi1 = mid; }
    float cnt = (float)(lo1 - lo0);
    float inv = 1.f / fmaxf(cnt, 1.f);

    float v[47];
#pragma unroll
    for (int cc = 0; cc < 32; cc++) v[cc] = d_gsum[g * 32 + cc] * inv;
#pragma unroll
    for (int f = 0; f < 15; f++) v[32 + f] = stats[g * 15 + f];
    float o = bm2[0];
    for (int k = 0; k < 32; k++) {
        float hsum = bm1[k];
#pragma unroll
        for (int i = 0; i < 47; i++) hsum = fmaf(v[i], Wm1[i * 32 + k], hsum);
        o = fmaf(fmaxf(hsum, 0.f), Wm2[k], o);
    }
    out[g] = o;
}

// ---------------- launch ----------------
extern "C" void kernel_launch(void* const* d_in, const int* in_sizes, int n_in,
                              void* d_out, int out_size)
{
    const float* x     = (const float*)d_in[0];
    const int*   ei    = (const int*)d_in[1];
    const int*   batch = (const int*)d_in[2];
    const float* stats = (const float*)d_in[3];
    const float* W1    = (const float*)d_in[4];
    const float* as1   = (const float*)d_in[5];
    const float* ad1   = (const float*)d_in[6];
    const float* b1    = (const float*)d_in[7];
    const float* W2    = (const float*)d_in[8];
    const float* as2   = (const float*)d_in[9];
    const float* ad2   = (const float*)d_in[10];
    const float* b2    = (const float*)d_in[11];
    const float* Wm1   = (const float*)d_in[12];
    const float* bm1   = (const float*)d_in[13];
    const float* Wm2   = (const float*)d_in[14];
    const float* bm2   = (const float*)d_in[15];

    int N = in_sizes[0] / 128;
    int E = in_sizes[1] / 2;
    int B = in_sizes[3] / 15;

    __half *Xh, *Wt1, *Wt2; __half2 *H1h; float *OUT2;
    cudaGetSymbolAddress((void**)&Xh,   d_Xh);
    cudaGetSymbolAddress((void**)&Wt1,  d_Wt1);
    cudaGetSymbolAddress((void**)&Wt2,  d_Wt2);
    cudaGetSymbolAddress((void**)&H1h,  d_H1h);
    cudaGetSymbolAddress((void**)&OUT2, d_OUT2);

    const int SMEM = 4 * 128 * 40 * (int)sizeof(__half);   // 40960
    static bool s_attr = false;
    if (!s_attr) {
        cudaFuncSetAttribute(k_gemm_att, cudaFuncAttributeMaxDynamicSharedMemorySize, SMEM);
        s_attr = true;
    }

    int gemmBlocks = (N + 127) / 128;
    int edgeBlocks = (E + 255) / 256;
    int fillBlocks = (E + N + 255) / 256;
    int aggBlocks  = (N + 3) / 4;
    int scanBlocks = (N + 1023) / 1024;

    k_init<<<256, 256>>>(x, W1, W2, N, B);

    k_deg  <<<edgeBlocks, 256>>>(ei, E);
    k_scan1<<<scanBlocks, 1024>>>(N);
    k_scan3<<<scanBlocks, 1024>>>(N);
    k_fill <<<fillBlocks, 256>>>(ei, E, N);

    k_gemm_att<<<gemmBlocks, 256, SMEM>>>(Xh, Wt1, as1, ad1, N);
    k_agg<false><<<aggBlocks, 128>>>(b1, H1h, N);

    k_gemm_att<<<gemmBlocks, 256, SMEM>>>((const __half*)H1h, Wt2, as2, ad2, N);
    k_agg<true><<<aggBlocks, 128>>>(b2, OUT2, N);

    k_pool<<<128, 256>>>(OUT2, batch, N);
    k_mlp<<<1, 128>>>(batch, N, stats, Wm1, bm1, Wm2, bm2, (float*)d_out, B);
}

// round 12
// speedup vs baseline: 1.0919x; 1.0919x over previous
#include <cuda_runtime.h>
#include <cuda_fp16.h>
#include <stdint.h>
#include <math.h>

#define NMAX 50000
#define EMAX 800000
#define BMAX 128

// ---------------- scratch ----------------
__device__ __half2 d_XHh [NMAX * 64];    // GEMM output fp16
__device__ __half2 d_H1h [NMAX * 64];    // layer-1 output fp16
__device__ __half  d_Wt1 [128 * 128];    // W1^T fp16 [n][k]
__device__ __half  d_Wt2 [128 * 128];    // W2^T fp16 [n][k]
__device__ float   d_ASRC[NMAX * 4];
__device__ float   d_ADST[NMAX * 4];
__device__ int     d_deg   [NMAX];
__device__ int     d_rowptr[NMAX + 1];
__device__ int     d_cursor[NMAX];
__device__ int     d_col   [EMAX + NMAX];
__device__ float   d_gsum  [BMAX * 32];
__device__ int     d_bsum  [64];

// ---------------- init + weight prep ----------------
__global__ void k_init(const float* __restrict__ W1, const float* __restrict__ W2,
                       int N, int B) {
    int i0 = blockIdx.x * blockDim.x + threadIdx.x;
    int stride = gridDim.x * blockDim.x;
    for (int t = i0; t < N; t += stride) d_deg[t] = 1;   // self loop pre-counted
    for (int t = i0; t < B * 32; t += stride) d_gsum[t] = 0.f;
    for (int t = i0; t < 16384; t += stride) {
        int n = t >> 7, k = t & 127;
        d_Wt1[n * 128 + k] = __float2half_rn(W1[k * 128 + n]);
        d_Wt2[n * 128 + k] = __float2half_rn(W2[k * 128 + n]);
    }
}

// ---------------- tensor-core GEMM + fused attention dots (round-9 sync version) ----------------
template <bool HIN>
__global__ void __launch_bounds__(256, 2) k_gemm_att(
    const void* __restrict__ Xv, const __half* __restrict__ Wt,
    const float* __restrict__ att_s, const float* __restrict__ att_d,
    int nrows)
{
    __shared__ __half Xs[128][40];
    __shared__ __half Ws[128][40];

    int tid = threadIdx.x;
    int wid = tid >> 5, lane = tid & 31;
    int g = lane >> 2, t = lane & 3;
    int wr = wid >> 1, wc = wid & 1;
    int rowBase = blockIdx.x * 128;

    float acc[2][8][4];
#pragma unroll
    for (int mi = 0; mi < 2; mi++)
#pragma unroll
        for (int ni = 0; ni < 8; ni++)
#pragma unroll
            for (int q = 0; q < 4; q++) acc[mi][ni][q] = 0.f;

    for (int k0 = 0; k0 < 128; k0 += 32) {
        if (HIN) {
            const uint4* Xh = (const uint4*)Xv;
#pragma unroll
            for (int it = 0; it < 2; it++) {
                int idx = tid + 256 * it;
                int r = idx >> 2;
                int c8 = (idx & 3) * 8;
                int gr = rowBase + r;
                uint4 v = (gr < nrows) ? Xh[gr * 16 + (k0 >> 3) + (c8 >> 3)]
                                       : make_uint4(0u, 0u, 0u, 0u);
                *(uint4*)&Xs[r][c8] = v;
            }
        } else {
            const float* X = (const float*)Xv;
#pragma unroll
            for (int it = 0; it < 4; it++) {
                int idx = tid + 256 * it;
                int r = idx >> 3;
                int c4 = (idx & 7) * 4;
                int gr = rowBase + r;
                float4 v = (gr < nrows) ? *(const float4*)&X[gr * 128 + k0 + c4]
                                        : make_float4(0.f, 0.f, 0.f, 0.f);
                __half2 h0 = __floats2half2_rn(v.x, v.y);
                __half2 h1 = __floats2half2_rn(v.z, v.w);
                uint2 p; p.x = *(uint32_t*)&h0; p.y = *(uint32_t*)&h1;
                *(uint2*)&Xs[r][c4] = p;
            }
        }
#pragma unroll
        for (int it = 0; it < 2; it++) {
            int idx = tid + 256 * it;
            int n = idx >> 2;
            int c8 = (idx & 3) * 8;
            *(uint4*)&Ws[n][c8] = *(const uint4*)&Wt[n * 128 + k0 + c8];
        }
        __syncthreads();
#pragma unroll
        for (int ks = 0; ks < 2; ks++) {
            int kb = ks * 16;
            uint32_t a[2][4];
#pragma unroll
            for (int mi = 0; mi < 2; mi++) {
                int ar = wr * 32 + mi * 16 + g;
                a[mi][0] = *(const uint32_t*)&Xs[ar][kb + 2 * t];
                a[mi][1] = *(const uint32_t*)&Xs[ar + 8][kb + 2 * t];
                a[mi][2] = *(const uint32_t*)&Xs[ar][kb + 2 * t + 8];
                a[mi][3] = *(const uint32_t*)&Xs[ar + 8][kb + 2 * t + 8];
            }
#pragma unroll
            for (int ni = 0; ni < 8; ni++) {
                int bn = wc * 64 + ni * 8 + g;
                uint32_t b0 = *(const uint32_t*)&Ws[bn][kb + 2 * t];
                uint32_t b1 = *(const uint32_t*)&Ws[bn][kb + 2 * t + 8];
#pragma unroll
                for (int mi = 0; mi < 2; mi++) {
                    asm volatile(
                        "mma.sync.aligned.m16n8k16.row.col.f32.f16.f16.f32 "
                        "{%0,%1,%2,%3}, {%4,%5,%6,%7}, {%8,%9}, {%0,%1,%2,%3};"
                        : "+f"(acc[mi][ni][0]), "+f"(acc[mi][ni][1]),
                          "+f"(acc[mi][ni][2]), "+f"(acc[mi][ni][3])
                        : "r"(a[mi][0]), "r"(a[mi][1]), "r"(a[mi][2]), "r"(a[mi][3]),
                          "r"(b0), "r"(b1));
                }
            }
        }
        __syncthreads();
    }

    // ---- epilogue: attention dots, direct global store ----
#pragma unroll
    for (int mi = 0; mi < 2; mi++) {
        float ps[2][2] = {{0.f, 0.f}, {0.f, 0.f}};
        float pd[2][2] = {{0.f, 0.f}, {0.f, 0.f}};
#pragma unroll
        for (int ni = 0; ni < 8; ni++) {
            int col = wc * 64 + ni * 8 + 2 * t;
            float s0 = att_s[col], s1 = att_s[col + 1];
            float dd0 = att_d[col], dd1 = att_d[col + 1];
            int hl = ni >> 2;
            ps[0][hl] += acc[mi][ni][0] * s0 + acc[mi][ni][1] * s1;
            ps[1][hl] += acc[mi][ni][2] * s0 + acc[mi][ni][3] * s1;
            pd[0][hl] += acc[mi][ni][0] * dd0 + acc[mi][ni][1] * dd1;
            pd[1][hl] += acc[mi][ni][2] * dd0 + acc[mi][ni][3] * dd1;
        }
#pragma unroll
        for (int o = 1; o <= 2; o <<= 1) {
#pragma unroll
            for (int rh = 0; rh < 2; rh++)
#pragma unroll
                for (int hl = 0; hl < 2; hl++) {
                    ps[rh][hl] += __shfl_xor_sync(0xffffffffu, ps[rh][hl], o);
                    pd[rh][hl] += __shfl_xor_sync(0xffffffffu, pd[rh][hl], o);
                }
        }
        if (t == 0) {
            int gr = rowBase + wr * 32 + mi * 16 + g;
            if (gr < nrows) {
                d_ASRC[gr * 4 + 2 * wc]     = ps[0][0];
                d_ASRC[gr * 4 + 2 * wc + 1] = ps[0][1];
                d_ADST[gr * 4 + 2 * wc]     = pd[0][0];
                d_ADST[gr * 4 + 2 * wc + 1] = pd[0][1];
            }
            if (gr + 8 < nrows) {
                d_ASRC[(gr + 8) * 4 + 2 * wc]     = ps[1][0];
                d_ASRC[(gr + 8) * 4 + 2 * wc + 1] = ps[1][1];
                d_ADST[(gr + 8) * 4 + 2 * wc]     = pd[1][0];
                d_ADST[(gr + 8) * 4 + 2 * wc + 1] = pd[1][1];
            }
        }
    }
#pragma unroll
    for (int mi = 0; mi < 2; mi++) {
        int r0 = rowBase + wr * 32 + mi * 16 + g;
#pragma unroll
        for (int ni = 0; ni < 8; ni++) {
            int cp = wc * 32 + ni * 4 + t;
            if (r0 < nrows)
                d_XHh[r0 * 64 + cp] = __floats2half2_rn(acc[mi][ni][0], acc[mi][ni][1]);
            if (r0 + 8 < nrows)
                d_XHh[(r0 + 8) * 64 + cp] = __floats2half2_rn(acc[mi][ni][2], acc[mi][ni][3]);
        }
    }
}

// ---------------- CSR build ----------------
__global__ void k_deg(const int* __restrict__ ei, int E) {
    int i = blockIdx.x * blockDim.x + threadIdx.x;
    if (i >= E) return;
    atomicAdd(&d_deg[ei[E + i]], 1);
}

__global__ void __launch_bounds__(1024) k_scan1(int N) {
    __shared__ int swarp[32];
    int b = blockIdx.x;
    int tid = threadIdx.x, lane = tid & 31, wid = tid >> 5;
    int i = b * 1024 + tid;
    int v = (i < N) ? d_deg[i] : 0;
    int x = v;
#pragma unroll
    for (int o = 1; o < 32; o <<= 1) {
        int t = __shfl_up_sync(0xffffffffu, x, o);
        if (lane >= o) x += t;
    }
    if (lane == 31) swarp[wid] = x;
    __syncthreads();
    if (wid == 0) {
        int y = swarp[lane];
#pragma unroll
        for (int o = 1; o < 32; o <<= 1) {
            int t = __shfl_up_sync(0xffffffffu, y, o);
            if (lane >= o) y += t;
        }
        swarp[lane] = y;
    }
    __syncthreads();
    int incl = x + (wid > 0 ? swarp[wid - 1] : 0);
    if (i < N) d_rowptr[i + 1] = incl;
    if (tid == 1023) d_bsum[b] = incl;
}

// fused phase 2+3 (validated round 11): full-warp 64-wide scan, no divergent shuffles
__global__ void __launch_bounds__(1024) k_scan3(int N) {
    __shared__ int s_incl[64];
    int b = blockIdx.x;
    int nb = gridDim.x;
    int tid = threadIdx.x;
    if (tid < 64) {
        int v = (tid < nb) ? d_bsum[tid] : 0;
        int x = v;
#pragma unroll
        for (int o = 1; o < 32; o <<= 1) {
            int t = __shfl_up_sync(0xffffffffu, x, o);
            if ((tid & 31) >= o) x += t;
        }
        s_incl[tid] = x;
    }
    __syncthreads();
    int base = (b < 32) ? 0 : s_incl[31];
    int off = base + s_incl[b] - d_bsum[b];
    int i = b * 1024 + tid;
    if (i >= N) return;
    int rp = d_rowptr[i + 1] + off;
    d_rowptr[i + 1] = rp;
    d_cursor[i] = rp - d_deg[i];
    if (i == 0) d_rowptr[0] = 0;
}

__global__ void k_fill(const int* __restrict__ ei, int E, int N) {
    int i = blockIdx.x * blockDim.x + threadIdx.x;
    int T = E + N;
    if (i >= T) return;
    if (i < E) {
        int s = ei[i], dd = ei[E + i];
        int pos = atomicAdd(&d_cursor[dd], 1);
        d_col[pos] = s;
    } else {
        int n = i - E;
        d_col[d_rowptr[n + 1] - 1] = n;
    }
}

// ---------------- GAT aggregation ----------------
// LAYER2 fuses graph mean-pool: block-level run compression -> ~32 atomics/block
template <bool LAYER2>
__global__ void __launch_bounds__(128) k_agg(
    const float* __restrict__ bias, void* __restrict__ OUT,
    const int* __restrict__ batch, int N)
{
    __shared__ float4 s_e4[4][32];
    __shared__ int    s_src[4][32];
    __shared__ float  s_out[4][32];
    __shared__ int    s_b[4];

    int tid = threadIdx.x;
    int w = tid >> 5, lane = tid & 31;
    int n = blockIdx.x * 4 + w;
    bool valid = (n < N);
    if (!LAYER2 && !valid) return;
    int h = lane >> 3;

    if (valid) {
        int start = d_rowptr[n], end = d_rowptr[n + 1];
        float4 ad = ((const float4*)d_ADST)[n];

        float m = -INFINITY, den = 0.f;
        float4 acc = make_float4(0.f, 0.f, 0.f, 0.f);
        const float* se = (const float*)&s_e4[w][0];
        const int*   ss = &s_src[w][0];
        const uint2* XH8 = (const uint2*)d_XHh;

        for (int k0 = start; k0 < end; k0 += 32) {
            int len = min(32, end - k0);
            float4 e4 = make_float4(-INFINITY, -INFINITY, -INFINITY, -INFINITY);
            int s = 0;
            if (lane < len) {
                s = __ldg(&d_col[k0 + lane]);
                float4 as = __ldg(&((const float4*)d_ASRC)[s]);
                e4.x = as.x + ad.x; e4.x = e4.x > 0.f ? e4.x : 0.2f * e4.x;
                e4.y = as.y + ad.y; e4.y = e4.y > 0.f ? e4.y : 0.2f * e4.y;
                e4.z = as.z + ad.z; e4.z = e4.z > 0.f ? e4.z : 0.2f * e4.z;
                e4.w = as.w + ad.w; e4.w = e4.w > 0.f ? e4.w : 0.2f * e4.w;
            }
            s_src[w][lane] = s;
            s_e4[w][lane] = e4;

            float4 mx = e4;
#pragma unroll
            for (int o = 16; o >= 1; o >>= 1) {
                mx.x = fmaxf(mx.x, __shfl_xor_sync(0xffffffffu, mx.x, o));
                mx.y = fmaxf(mx.y, __shfl_xor_sync(0xffffffffu, mx.y, o));
                mx.z = fmaxf(mx.z, __shfl_xor_sync(0xffffffffu, mx.z, o));
                mx.w = fmaxf(mx.w, __shfl_xor_sync(0xffffffffu, mx.w, o));
            }
            float cmh = (h == 0) ? mx.x : (h == 1) ? mx.y : (h == 2) ? mx.z : mx.w;
            float cm = fmaxf(m, cmh);
            float scale = __expf(m - cm);
            acc.x *= scale; acc.y *= scale; acc.z *= scale; acc.w *= scale;
            den *= scale;

            __syncwarp();
#pragma unroll 4
            for (int j = 0; j < len; j++) {
                float p = __expf(se[j * 4 + h] - cm);
                den += p;
                uint2 r = __ldg(&XH8[ss[j] * 32 + lane]);
                float2 f0 = __half22float2(*(const __half2*)&r.x);
                float2 f1 = __half22float2(*(const __half2*)&r.y);
                acc.x = fmaf(p, f0.x, acc.x);
                acc.y = fmaf(p, f0.y, acc.y);
                acc.z = fmaf(p, f1.x, acc.z);
                acc.w = fmaf(p, f1.y, acc.w);
            }
            m = cm;
            __syncwarp();
        }

        float inv = 1.f / (den + 1e-16f);
        float4 val = make_float4(acc.x * inv, acc.y * inv, acc.z * inv, acc.w * inv);

        if (!LAYER2) {
            float4 b4 = ((const float4*)bias)[lane];
            val.x = fmaxf(val.x + b4.x, 0.f);
            val.y = fmaxf(val.y + b4.y, 0.f);
            val.z = fmaxf(val.z + b4.z, 0.f);
            val.w = fmaxf(val.w + b4.w, 0.f);
            __half2 h0 = __floats2half2_rn(val.x, val.y);
            __half2 h1 = __floats2half2_rn(val.z, val.w);
            uint2 p; p.x = *(uint32_t*)&h0; p.y = *(uint32_t*)&h1;
            ((uint2*)OUT)[n * 32 + lane] = p;     // fp16 H1
        } else {
            // mean over 4 heads -> 32 channels
#pragma unroll
            for (int o = 8; o <= 16; o <<= 1) {
                val.x += __shfl_xor_sync(0xffffffffu, val.x, o);
                val.y += __shfl_xor_sync(0xffffffffu, val.y, o);
                val.z += __shfl_xor_sync(0xffffffffu, val.z, o);
                val.w += __shfl_xor_sync(0xffffffffu, val.w, o);
            }
            if (lane < 8) {
                float4 b4 = ((const float4*)bias)[lane];
                s_out[w][lane * 4 + 0] = 0.25f * val.x + b4.x;
                s_out[w][lane * 4 + 1] = 0.25f * val.y + b4.y;
                s_out[w][lane * 4 + 2] = 0.25f * val.z + b4.z;
                s_out[w][lane * 4 + 3] = 0.25f * val.w + b4.w;
            }
            if (lane == 0) s_b[w] = batch[n];
        }
    } else if (LAYER2 && lane == 0) {
        s_b[w] = -1;
    }

    if (LAYER2) {
        __syncthreads();
        if (tid < 32) {
            float sum = 0.f;
            int curb = -1;
#pragma unroll
            for (int w2 = 0; w2 < 4; w2++) {
                int b = s_b[w2];
                if (b < 0) continue;
                if (b != curb) {
                    if (curb >= 0) atomicAdd(&d_gsum[curb * 32 + tid], sum);
                    curb = b; sum = 0.f;
                }
                sum += s_out[w2][tid];
            }
            if (curb >= 0) atomicAdd(&d_gsum[curb * 32 + tid], sum);
        }
    }
}

// ---------------- final MLP ----------------
__global__ void k_mlp(const int* __restrict__ batch, int N,
                      const float* __restrict__ stats,
                      const float* __restrict__ Wm1, const float* __restrict__ bm1,
                      const float* __restrict__ Wm2, const float* __restrict__ bm2,
                      float* __restrict__ out, int B)
{
    int g = threadIdx.x;
    if (g >= B) return;
    int lo0 = 0, hi0 = N;
    while (lo0 < hi0) { int mid = (lo0 + hi0) >> 1; if (batch[mid] < g) lo0 = mid + 1; else hi0 = mid; }
    int lo1 = lo0, hi1 = N;
    while (lo1 < hi1) { int mid = (lo1 + hi1) >> 1; if (batch[mid] < g + 1) lo1 = mid + 1; else hi1 = mid; }
    float cnt = (float)(lo1 - lo0);
    float inv = 1.f / fmaxf(cnt, 1.f);

    float v[47];
#pragma unroll
    for (int cc = 0; cc < 32; cc++) v[cc] = d_gsum[g * 32 + cc] * inv;
#pragma unroll
    for (int f = 0; f < 15; f++) v[32 + f] = stats[g * 15 + f];
    float o = bm2[0];
    for (int k = 0; k < 32; k++) {
        float hsum = bm1[k];
#pragma unroll
        for (int i = 0; i < 47; i++) hsum = fmaf(v[i], Wm1[i * 32 + k], hsum);
        o = fmaf(fmaxf(hsum, 0.f), Wm2[k], o);
    }
    out[g] = o;
}

// ---------------- launch ----------------
extern "C" void kernel_launch(void* const* d_in, const int* in_sizes, int n_in,
                              void* d_out, int out_size)
{
    const float* x     = (const float*)d_in[0];
    const int*   ei    = (const int*)d_in[1];
    const int*   batch = (const int*)d_in[2];
    const float* stats = (const float*)d_in[3];
    const float* W1    = (const float*)d_in[4];
    const float* as1   = (const float*)d_in[5];
    const float* ad1   = (const float*)d_in[6];
    const float* b1    = (const float*)d_in[7];
    const float* W2    = (const float*)d_in[8];
    const float* as2   = (const float*)d_in[9];
    const float* ad2   = (const float*)d_in[10];
    const float* b2    = (const float*)d_in[11];
    const float* Wm1   = (const float*)d_in[12];
    const float* bm1   = (const float*)d_in[13];
    const float* Wm2   = (const float*)d_in[14];
    const float* bm2   = (const float*)d_in[15];

    int N = in_sizes[0] / 128;
    int E = in_sizes[1] / 2;
    int B = in_sizes[3] / 15;

    __half *Wt1, *Wt2; __half2 *H1h;
    cudaGetSymbolAddress((void**)&Wt1, d_Wt1);
    cudaGetSymbolAddress((void**)&Wt2, d_Wt2);
    cudaGetSymbolAddress((void**)&H1h, d_H1h);

    int gemmBlocks = (N + 127) / 128;
    int edgeBlocks = (E + 255) / 256;
    int fillBlocks = (E + N + 255) / 256;
    int aggBlocks  = (N + 3) / 4;
    int scanBlocks = (N + 1023) / 1024;

    k_init<<<128, 256>>>(W1, W2, N, B);

    k_deg  <<<edgeBlocks, 256>>>(ei, E);
    k_scan1<<<scanBlocks, 1024>>>(N);
    k_scan3<<<scanBlocks, 1024>>>(N);
    k_fill <<<fillBlocks, 256>>>(ei, E, N);

    k_gemm_att<false><<<gemmBlocks, 256>>>(x, Wt1, as1, ad1, N);
    k_agg<false><<<aggBlocks, 128>>>(b1, H1h, batch, N);

    k_gemm_att<true><<<gemmBlocks, 256>>>(H1h, Wt2, as2, ad2, N);
    k_agg<true><<<aggBlocks, 128>>>(b2, nullptr, batch, N);   // pool fused

    k_mlp<<<1, 128>>>(batch, N, stats, Wm1, bm1, Wm2, bm2, (float*)d_out, B);
}